// round 15
// baseline (speedup 1.0000x reference)
#include <cuda_runtime.h>
#include <cstdint>

#define N_ATOMS 131072
#define CH      256
#define D_DOM   16384
#define M_MSG   65536
#define E_EDGE  262144

// ---------------- scratch (device globals; no allocations allowed) ----------
__device__ float g_xc[(size_t)N_ATOMS * CH];   // x pre-rounded to tf32
__device__ float g_wc[458752];                 // all weights pre-rounded to tf32
__device__ float g_xa[(size_t)N_ATOMS * CH];   // x @ W0^T
__device__ float g_msg[(size_t)M_MSG * CH];    // segsum(x[src], ii)   (tf32-rounded)
__device__ float g_msgb[(size_t)M_MSG * CH];   // msg @ W1^T + u2[dme0]
__device__ float g_xinv[(size_t)D_DOM * CH];   // segmean(x, dom)      (tf32-rounded)
__device__ float g_u2[(size_t)D_DOM * CH];     // x_inv @ W2^T
__device__ float g_r1[(size_t)D_DOM * CH];     // segsum(msg, dme1)
__device__ float g_r2[(size_t)D_DOM * CH];     // segsum(x_inv[dme0], dme1)
__device__ float g_invt[(size_t)D_DOM * CH];   // xinv@Wlin_inv + r1@W4a + r2@W4b

// weight offsets inside g_wc (floats)
#define WC_TFI  0          // Wtf_int  [256 x 768]
#define WC_TFV  196608     // Wtf_inv  [256 x 512]
#define WC_LINV 327680     // Wlin_inv [256 x 256]
#define WC_LID  393216     // Wlin_id  [256 x 256]

// ---------------- helpers ----------------------------------------------------
__device__ __forceinline__ float to_tf32(float f) {
    float r; asm("cvt.rna.tf32.f32 %0, %1;" : "=f"(r) : "f"(f)); return r;
}
__device__ __forceinline__ void mma_tf32(float* c, const uint32_t* a, const uint32_t* b) {
    asm volatile("mma.sync.aligned.m16n8k8.row.col.f32.tf32.tf32.f32 "
                 "{%0,%1,%2,%3}, {%4,%5,%6,%7}, {%8,%9}, {%0,%1,%2,%3};"
                 : "+f"(c[0]), "+f"(c[1]), "+f"(c[2]), "+f"(c[3])
                 : "r"(a[0]), "r"(a[1]), "r"(a[2]), "r"(a[3]), "r"(b[0]), "r"(b[1]));
}
__device__ __forceinline__ int lower_bound_dev(const int* __restrict__ a, int n, int v) {
    int lo = 0, hi = n;
    while (lo < hi) { int mid = (lo + hi) >> 1; if (a[mid] < v) lo = mid + 1; else hi = mid; }
    return lo;
}
__device__ __forceinline__ void red_add_v4(float* p, float4 v) {
    asm volatile("red.global.add.v4.f32 [%0], {%1,%2,%3,%4};"
                 :: "l"(p), "f"(v.x), "f"(v.y), "f"(v.z), "f"(v.w) : "memory");
}
__device__ __forceinline__ uint32_t smem_u32(const void* p) {
    uint32_t a;
    asm("{ .reg .u64 t; cvta.to.shared.u64 t, %1; cvt.u32.u64 %0, t; }" : "=r"(a) : "l"(p));
    return a;
}
__device__ __forceinline__ void cp_async16(uint32_t s, const void* g) {
    asm volatile("cp.async.cg.shared.global [%0], [%1], 16;" :: "r"(s), "l"(g) : "memory");
}
#define CP_COMMIT()  asm volatile("cp.async.commit_group;" ::: "memory")
#define CP_WAIT1()   asm volatile("cp.async.wait_group 1;" ::: "memory")

// ---------------- tf32 convert (float4) ---------------------------------------
__global__ void conv4_kernel(const float* __restrict__ src, float* __restrict__ dst) {
    int i = blockIdx.x * blockDim.x + threadIdx.x;
    float4 v = ((const float4*)src)[i];
    v.x = to_tf32(v.x); v.y = to_tf32(v.y); v.z = to_tf32(v.z); v.w = to_tf32(v.w);
    ((float4*)dst)[i] = v;
}

// ---------------- tf32 mma.sync GEMM — cp.async 3-stage pipeline --------------
// C = A1@B1^T (+A2@B2^T)(+A3@B3^T); optional epilogue C[i,:] += Gadd[gidx[i],:].
// All A/B values must already be tf32-rounded (MMA truncation is then exact).
// CTA tile 128x256; 8 warps 2x4; warp tile 64x64 = 4x8 m16n8k8; K chunk 32.
#define ASTRIDE 36
#define ABF (128 * ASTRIDE)              // A floats per stage
#define STGF ((128 + 256) * ASTRIDE)     // floats per stage (A + B)
#define NSTAGE 3
#define SMEMSZ (NSTAGE * STGF * 4)

__global__ __launch_bounds__(256, 1)
void mma_gemm(const float* __restrict__ A1, const float* __restrict__ B1, int ldb1,
              const float* __restrict__ A2, const float* __restrict__ B2, int ldb2,
              const float* __restrict__ A3, const float* __restrict__ B3, int ldb3,
              float* __restrict__ C,
              const float* __restrict__ Gadd, const int* __restrict__ gidx)
{
    extern __shared__ float sm[];
    uint32_t smb = smem_u32(sm);

    int tid = threadIdx.x, lane = tid & 31, wid = tid >> 5;
    int wm = (wid >> 2) * 64, wn = (wid & 3) * 64;
    int row0 = blockIdx.x * 128;
    int rr = tid >> 3, c4 = tid & 7;     // copy mapping: 32 rows x 8 float4
    int nch = 8 + (A2 ? 8 : 0) + (A3 ? 8 : 0);

    float acc[4][8][4];
#pragma unroll
    for (int i = 0; i < 4; i++)
#pragma unroll
        for (int j = 0; j < 8; j++)
#pragma unroll
            for (int q = 0; q < 4; q++) acc[i][j][q] = 0.f;

    uint32_t soff = (uint32_t)(rr * ASTRIDE + c4 * 4) * 4;

    auto issue = [&](int kc) {
        const float* A = (kc < 8) ? A1 : (kc < 16) ? A2 : A3;
        const float* B = (kc < 8) ? B1 : (kc < 16) ? B2 : B3;
        int ldb = (kc < 8) ? ldb1 : (kc < 16) ? ldb2 : ldb3;
        int k0 = (kc & 7) * 32;
        uint32_t ab = smb + (uint32_t)((kc % NSTAGE) * STGF) * 4;
        uint32_t bb = ab + (uint32_t)ABF * 4;
#pragma unroll
        for (int p = 0; p < 4; p++)
            cp_async16(ab + (uint32_t)(p * 32 * ASTRIDE) * 4 + soff,
                       A + (size_t)(row0 + p * 32 + rr) * 256 + k0 + c4 * 4);
#pragma unroll
        for (int p = 0; p < 8; p++)
            cp_async16(bb + (uint32_t)(p * 32 * ASTRIDE) * 4 + soff,
                       B + (size_t)(p * 32 + rr) * ldb + k0 + c4 * 4);
    };

    auto compute = [&](int st) {
        const float* a = sm + st * STGF;
        const float* b = a + ABF;
        int r = lane >> 2, c = lane & 3;
#pragma unroll
        for (int kk = 0; kk < 4; kk++) {
            uint32_t af[4][4], bf[8][2];
#pragma unroll
            for (int im = 0; im < 4; im++) {
                const float* ap = a + (wm + im * 16 + r) * ASTRIDE + kk * 8 + c;
                af[im][0] = __float_as_uint(ap[0]);
                af[im][1] = __float_as_uint(ap[8 * ASTRIDE]);
                af[im][2] = __float_as_uint(ap[4]);
                af[im][3] = __float_as_uint(ap[8 * ASTRIDE + 4]);
            }
#pragma unroll
            for (int jn = 0; jn < 8; jn++) {
                const float* bp = b + (wn + jn * 8 + r) * ASTRIDE + kk * 8 + c;
                bf[jn][0] = __float_as_uint(bp[0]);
                bf[jn][1] = __float_as_uint(bp[4]);
            }
#pragma unroll
            for (int im = 0; im < 4; im++)
#pragma unroll
                for (int jn = 0; jn < 8; jn++)
                    mma_tf32(acc[im][jn], af[im], bf[jn]);
        }
    };

    // prologue: 2 stages in flight
    issue(0); CP_COMMIT();
    issue(1); CP_COMMIT();
    CP_WAIT1();             // stage 0 landed (own groups)
    __syncthreads();        // all threads' stage-0 data visible

    for (int kc = 0; kc < nch; kc++) {
        if (kc + 2 < nch) issue(kc + 2);
        CP_COMMIT();        // uniform group count (empty commits at tail)
        compute(kc % NSTAGE);
        CP_WAIT1();         // stage kc+1 landed; stage kc+2 may be in flight
        __syncthreads();    // everyone done with stage kc -> its buffer reusable
    }

    // epilogue (+ optional gather-add of Gadd[gidx[row]])
    int r = lane >> 2, cc = (lane & 3) * 2;
#pragma unroll
    for (int im = 0; im < 4; im++) {
        int rowA = row0 + wm + im * 16 + r;
        int rowB = rowA + 8;
        const float* ga = nullptr; const float* gb = nullptr;
        if (gidx) {
            ga = Gadd + (size_t)gidx[rowA] * 256;
            gb = Gadd + (size_t)gidx[rowB] * 256;
        }
#pragma unroll
        for (int jn = 0; jn < 8; jn++) {
            int col = wn + jn * 8 + cc;
            float2 v0 = make_float2(acc[im][jn][0], acc[im][jn][1]);
            float2 v1 = make_float2(acc[im][jn][2], acc[im][jn][3]);
            if (gidx) {
                float2 a0 = *(const float2*)(ga + col);
                float2 a1 = *(const float2*)(gb + col);
                v0.x += a0.x; v0.y += a0.y; v1.x += a1.x; v1.y += a1.y;
            }
            *(float2*)(C + (size_t)rowA * 256 + col) = v0;
            *(float2*)(C + (size_t)rowB * 256 + col) = v1;
        }
    }
}

// ---------------- segment reductions: 64 threads, float4, tf32-rounded out ---
__global__ __launch_bounds__(64)
void segmean_kernel(const float* __restrict__ x, const int* __restrict__ dom) {
    __shared__ int s_lo, s_hi;
    int d = blockIdx.x;
    if (threadIdx.x == 0) {
        s_lo = lower_bound_dev(dom, N_ATOMS, d);
        s_hi = lower_bound_dev(dom, N_ATOMS, d + 1);
    }
    __syncthreads();
    int lo = s_lo, hi = s_hi, c = threadIdx.x;
    float4 s = make_float4(0.f, 0.f, 0.f, 0.f);
    for (int r = lo; r < hi; r++) {
        float4 v = ((const float4*)x)[(size_t)r * 64 + c];
        s.x += v.x; s.y += v.y; s.z += v.z; s.w += v.w;
    }
    int cnt = hi - lo;
    float inv = 1.f / (float)(cnt > 0 ? cnt : 1);
    s.x = to_tf32(s.x * inv); s.y = to_tf32(s.y * inv);
    s.z = to_tf32(s.z * inv); s.w = to_tf32(s.w * inv);
    ((float4*)g_xinv)[(size_t)d * 64 + c] = s;
}

__global__ __launch_bounds__(64)
void segmsg_kernel(const float* __restrict__ x, const int* __restrict__ ii,
                   const int* __restrict__ src) {
    __shared__ int s_lo, s_hi;
    int m = blockIdx.x;
    if (threadIdx.x == 0) {
        s_lo = lower_bound_dev(ii, E_EDGE, m);
        s_hi = lower_bound_dev(ii, E_EDGE, m + 1);
    }
    __syncthreads();
    int lo = s_lo, hi = s_hi, c = threadIdx.x;
    float4 s = make_float4(0.f, 0.f, 0.f, 0.f);
    for (int e = lo; e < hi; e++) {
        float4 v = ((const float4*)x)[(size_t)src[e] * 64 + c];
        s.x += v.x; s.y += v.y; s.z += v.z; s.w += v.w;
    }
    s.x = to_tf32(s.x); s.y = to_tf32(s.y); s.z = to_tf32(s.z); s.w = to_tf32(s.w);
    ((float4*)g_msg)[(size_t)m * 64 + c] = s;
}

__global__ void dom_scatter_kernel(const int* __restrict__ dme) {
    int m = blockIdx.x * 4 + (threadIdx.x >> 6);
    int c = threadIdx.x & 63;
    int d0 = dme[m];
    int d1 = dme[M_MSG + m];
    float4 a = ((const float4*)g_msg)[(size_t)m * 64 + c];
    float4 b = ((const float4*)g_xinv)[(size_t)d0 * 64 + c];
    red_add_v4(&g_r1[((size_t)d1 * 64 + c) * 4], a);
    red_add_v4(&g_r2[((size_t)d1 * 64 + c) * 4], b);
}

// out[tgt[e]] += xa[src[e]] + msgb[ii[e]]    (msgb already includes u2[dme0])
__global__ void edge_scatter_kernel(const int* __restrict__ nme, const int* __restrict__ ii,
                                    float* __restrict__ out) {
    int e = blockIdx.x * 4 + (threadIdx.x >> 6);
    int c = threadIdx.x & 63;
    int s = nme[e];
    int t = nme[E_EDGE + e];
    int m = ii[e];
    float4 a = ((const float4*)g_xa)[(size_t)s * 64 + c];
    float4 b = ((const float4*)g_msgb)[(size_t)m * 64 + c];
    float4 v = make_float4(a.x + b.x, a.y + b.y, a.z + b.z, a.w + b.w);
    red_add_v4(out + (size_t)t * 256 + c * 4, v);
}

// ---------------- launch ------------------------------------------------------
extern "C" void kernel_launch(void* const* d_in, const int* in_sizes, int n_in,
                              void* d_out, int out_size) {
    const float* x        = (const float*)d_in[0];
    const int*   dom      = (const int*)d_in[1];
    const int*   nme      = (const int*)d_in[2];   // [2, E] : src then tgt
    const int*   ii       = (const int*)d_in[3];
    const int*   dme      = (const int*)d_in[4];   // [2, M] : dme0 then dme1
    const float* Wtf_int  = (const float*)d_in[5]; // [256, 768]
    const float* Wtf_inv  = (const float*)d_in[6]; // [256, 512]
    const float* Wlin_inv = (const float*)d_in[7]; // [256, 256]
    const float* Wlin_id  = (const float*)d_in[8]; // [256, 256]
    float* out = (float*)d_out;

    float *xc, *wc, *xa, *msg, *msgb, *xinv, *u2, *r1, *r2, *invt;
    cudaGetSymbolAddress((void**)&xc,   g_xc);
    cudaGetSymbolAddress((void**)&wc,   g_wc);
    cudaGetSymbolAddress((void**)&xa,   g_xa);
    cudaGetSymbolAddress((void**)&msg,  g_msg);
    cudaGetSymbolAddress((void**)&msgb, g_msgb);
    cudaGetSymbolAddress((void**)&xinv, g_xinv);
    cudaGetSymbolAddress((void**)&u2,   g_u2);
    cudaGetSymbolAddress((void**)&r1,   g_r1);
    cudaGetSymbolAddress((void**)&r2,   g_r2);
    cudaGetSymbolAddress((void**)&invt, g_invt);

    cudaFuncSetAttribute(mma_gemm, cudaFuncAttributeMaxDynamicSharedMemorySize, SMEMSZ);

    // pre-round x and weights to tf32 (keeps MMA truncation == RNA rounding)
    conv4_kernel<<<(N_ATOMS * CH / 4) / 256, 256>>>(x, xc);
    conv4_kernel<<<192, 256>>>(Wtf_int,  wc + WC_TFI);
    conv4_kernel<<<128, 256>>>(Wtf_inv,  wc + WC_TFV);
    conv4_kernel<<<64,  256>>>(Wlin_inv, wc + WC_LINV);
    conv4_kernel<<<64,  256>>>(Wlin_id,  wc + WC_LID);

    // segment reductions (sorted indicators -> binary-searched ranges)
    cudaMemsetAsync(r1, 0, (size_t)D_DOM * CH * sizeof(float), 0);
    cudaMemsetAsync(r2, 0, (size_t)D_DOM * CH * sizeof(float), 0);
    segmean_kernel<<<D_DOM, 64>>>(x, dom);
    segmsg_kernel<<<M_MSG, 64>>>(x, ii, nme);

    // r1 = segsum(msg, dme1); r2 = segsum(x_inv[dme0], dme1)
    dom_scatter_kernel<<<M_MSG / 4, 256>>>(dme);

    // u2 = xinv@W2^T
    mma_gemm<<<D_DOM / 128, 256, SMEMSZ>>>(xinv, wc + WC_TFI + 512, 768,
                                           nullptr, nullptr, 0, nullptr, nullptr, 0,
                                           u2, nullptr, nullptr);
    // invt = xinv@Wlin_inv^T + r1@W4a^T + r2@W4b^T   (triple-A GEMM)
    mma_gemm<<<D_DOM / 128, 256, SMEMSZ>>>(xinv, wc + WC_LINV, 256,
                                           r1, wc + WC_TFV, 512,
                                           r2, wc + WC_TFV + 256, 512,
                                           invt, nullptr, nullptr);
    // out = x@Wlin_id^T + invt[dom]   (epilogue gather-add)
    mma_gemm<<<N_ATOMS / 128, 256, SMEMSZ>>>(xc, wc + WC_LID, 256,
                                             nullptr, nullptr, 0, nullptr, nullptr, 0,
                                             out, invt, dom);
    // xa = x@W0^T
    mma_gemm<<<N_ATOMS / 128, 256, SMEMSZ>>>(xc, wc + WC_TFI, 768,
                                             nullptr, nullptr, 0, nullptr, nullptr, 0,
                                             xa, nullptr, nullptr);
    // msgb = msg@W1^T + u2[dme0]   (fused gather-add epilogue)
    mma_gemm<<<M_MSG / 128, 256, SMEMSZ>>>(msg, wc + WC_TFI + 256, 768,
                                           nullptr, nullptr, 0, nullptr, nullptr, 0,
                                           msgb, u2, dme);

    // single fused edge scatter
    edge_scatter_kernel<<<E_EDGE / 4, 256>>>(nme, ii, out);
}

// round 16
// speedup vs baseline: 1.0197x; 1.0197x over previous
#include <cuda_runtime.h>
#include <cstdint>

#define N_ATOMS 131072
#define CH      256
#define D_DOM   16384
#define M_MSG   65536
#define E_EDGE  262144

// ---------------- scratch (device globals; no allocations allowed) ----------
__device__ float g_xc[(size_t)N_ATOMS * CH];   // x pre-rounded to tf32 (by segmean)
__device__ float g_wc[458752];                 // all weights pre-rounded to tf32
__device__ float g_xa[(size_t)N_ATOMS * CH];   // x @ W0^T
__device__ float g_msg[(size_t)M_MSG * CH];    // segsum(x[src], ii)   (tf32-rounded)
__device__ float g_msgb[(size_t)M_MSG * CH];   // msg @ W1^T + u2[dme0]
__device__ float g_xinv[(size_t)D_DOM * CH];   // segmean(x, dom)      (tf32-rounded)
__device__ float g_u2[(size_t)D_DOM * CH];     // x_inv @ W2^T
__device__ float g_r1[(size_t)D_DOM * CH];     // segsum(msg, dme1)
__device__ float g_r2[(size_t)D_DOM * CH];     // segsum(x_inv[dme0], dme1)
__device__ float g_invt[(size_t)D_DOM * CH];   // xinv@Wlin_inv + r1@W4a + r2@W4b

// weight offsets inside g_wc (floats)
#define WC_TFI  0          // Wtf_int  [256 x 768]
#define WC_TFV  196608     // Wtf_inv  [256 x 512]
#define WC_LINV 327680     // Wlin_inv [256 x 256]
#define WC_LID  393216     // Wlin_id  [256 x 256]

// ---------------- helpers ----------------------------------------------------
__device__ __forceinline__ float to_tf32(float f) {
    float r; asm("cvt.rna.tf32.f32 %0, %1;" : "=f"(r) : "f"(f)); return r;
}
__device__ __forceinline__ void mma_tf32(float* c, const uint32_t* a, const uint32_t* b) {
    asm volatile("mma.sync.aligned.m16n8k8.row.col.f32.tf32.tf32.f32 "
                 "{%0,%1,%2,%3}, {%4,%5,%6,%7}, {%8,%9}, {%0,%1,%2,%3};"
                 : "+f"(c[0]), "+f"(c[1]), "+f"(c[2]), "+f"(c[3])
                 : "r"(a[0]), "r"(a[1]), "r"(a[2]), "r"(a[3]), "r"(b[0]), "r"(b[1]));
}
__device__ __forceinline__ int lower_bound_dev(const int* __restrict__ a, int n, int v) {
    int lo = 0, hi = n;
    while (lo < hi) { int mid = (lo + hi) >> 1; if (a[mid] < v) lo = mid + 1; else hi = mid; }
    return lo;
}
__device__ __forceinline__ void red_add_v4(float* p, float4 v) {
    asm volatile("red.global.add.v4.f32 [%0], {%1,%2,%3,%4};"
                 :: "l"(p), "f"(v.x), "f"(v.y), "f"(v.z), "f"(v.w) : "memory");
}
__device__ __forceinline__ uint32_t smem_u32(const void* p) {
    uint32_t a;
    asm("{ .reg .u64 t; cvta.to.shared.u64 t, %1; cvt.u32.u64 %0, t; }" : "=r"(a) : "l"(p));
    return a;
}
__device__ __forceinline__ void cp_async16(uint32_t s, const void* g) {
    asm volatile("cp.async.cg.shared.global [%0], [%1], 16;" :: "r"(s), "l"(g) : "memory");
}
#define CP_COMMIT()  asm volatile("cp.async.commit_group;" ::: "memory")
#define CP_WAIT1()   asm volatile("cp.async.wait_group 1;" ::: "memory")

// ---------------- tf32 convert (float4), for weights only ---------------------
__global__ void conv4_kernel(const float* __restrict__ src, float* __restrict__ dst) {
    int i = blockIdx.x * blockDim.x + threadIdx.x;
    float4 v = ((const float4*)src)[i];
    v.x = to_tf32(v.x); v.y = to_tf32(v.y); v.z = to_tf32(v.z); v.w = to_tf32(v.w);
    ((float4*)dst)[i] = v;
}

// ---------------- tf32 mma.sync GEMM — cp.async 3-stage, 512 threads ----------
// C = A1@B1^T (+A2@B2^T)(+A3@B3^T); optional epilogue C[i,:] += Gadd[gidx[i],:].
// All A/B values must already be tf32-rounded (MMA truncation is then exact).
// CTA tile 128x256; 16 warps in 4(row)x4(col) grid; warp tile 32x64 = 2x8 atoms.
// K chunk 32; 3-stage cp.async ring; 36-float row stride.
#define ASTRIDE 36
#define ABF (128 * ASTRIDE)              // A floats per stage
#define STGF ((128 + 256) * ASTRIDE)     // floats per stage (A + B)
#define NSTAGE 3
#define SMEMSZ (NSTAGE * STGF * 4)

__global__ __launch_bounds__(512, 1)
void mma_gemm(const float* __restrict__ A1, const float* __restrict__ B1, int ldb1,
              const float* __restrict__ A2, const float* __restrict__ B2, int ldb2,
              const float* __restrict__ A3, const float* __restrict__ B3, int ldb3,
              float* __restrict__ C,
              const float* __restrict__ Gadd, const int* __restrict__ gidx)
{
    extern __shared__ float sm[];
    uint32_t smb = smem_u32(sm);

    int tid = threadIdx.x, lane = tid & 31, wid = tid >> 5;
    int wm = (wid >> 2) * 32, wn = (wid & 3) * 64;
    int row0 = blockIdx.x * 128;
    int rr = tid >> 3, c4 = tid & 7;     // copy mapping: 64 rows x 8 float4 per pass
    int nch = 8 + (A2 ? 8 : 0) + (A3 ? 8 : 0);

    float acc[2][8][4];
#pragma unroll
    for (int i = 0; i < 2; i++)
#pragma unroll
        for (int j = 0; j < 8; j++)
#pragma unroll
            for (int q = 0; q < 4; q++) acc[i][j][q] = 0.f;

    uint32_t soff = (uint32_t)(rr * ASTRIDE + c4 * 4) * 4;

    auto issue = [&](int kc) {
        const float* A = (kc < 8) ? A1 : (kc < 16) ? A2 : A3;
        const float* B = (kc < 8) ? B1 : (kc < 16) ? B2 : B3;
        int ldb = (kc < 8) ? ldb1 : (kc < 16) ? ldb2 : ldb3;
        int k0 = (kc & 7) * 32;
        uint32_t ab = smb + (uint32_t)((kc % NSTAGE) * STGF) * 4;
        uint32_t bb = ab + (uint32_t)ABF * 4;
#pragma unroll
        for (int p = 0; p < 2; p++)
            cp_async16(ab + (uint32_t)(p * 64 * ASTRIDE) * 4 + soff,
                       A + (size_t)(row0 + p * 64 + rr) * 256 + k0 + c4 * 4);
#pragma unroll
        for (int p = 0; p < 4; p++)
            cp_async16(bb + (uint32_t)(p * 64 * ASTRIDE) * 4 + soff,
                       B + (size_t)(p * 64 + rr) * ldb + k0 + c4 * 4);
    };

    auto compute = [&](int st) {
        const float* a = sm + st * STGF;
        const float* b = a + ABF;
        int r = lane >> 2, c = lane & 3;
#pragma unroll
        for (int kk = 0; kk < 4; kk++) {
            uint32_t af[2][4], bf[8][2];
#pragma unroll
            for (int im = 0; im < 2; im++) {
                const float* ap = a + (wm + im * 16 + r) * ASTRIDE + kk * 8 + c;
                af[im][0] = __float_as_uint(ap[0]);
                af[im][1] = __float_as_uint(ap[8 * ASTRIDE]);
                af[im][2] = __float_as_uint(ap[4]);
                af[im][3] = __float_as_uint(ap[8 * ASTRIDE + 4]);
            }
#pragma unroll
            for (int jn = 0; jn < 8; jn++) {
                const float* bp = b + (wn + jn * 8 + r) * ASTRIDE + kk * 8 + c;
                bf[jn][0] = __float_as_uint(bp[0]);
                bf[jn][1] = __float_as_uint(bp[4]);
            }
#pragma unroll
            for (int im = 0; im < 2; im++)
#pragma unroll
                for (int jn = 0; jn < 8; jn++)
                    mma_tf32(acc[im][jn], af[im], bf[jn]);
        }
    };

    // prologue: 2 stages in flight
    issue(0); CP_COMMIT();
    issue(1); CP_COMMIT();
    CP_WAIT1();             // own stage-0 copies landed
    __syncthreads();        // all threads' stage-0 data visible

    for (int kc = 0; kc < nch; kc++) {
        if (kc + 2 < nch) issue(kc + 2);
        CP_COMMIT();        // uniform group count (empty commits at tail)
        compute(kc % NSTAGE);
        CP_WAIT1();         // stage kc+1 landed; stage kc+2 may be in flight
        __syncthreads();    // everyone done with stage kc -> buffer reusable
    }

    // epilogue (+ optional gather-add of Gadd[gidx[row]])
    int r = lane >> 2, cc = (lane & 3) * 2;
#pragma unroll
    for (int im = 0; im < 2; im++) {
        int rowA = row0 + wm + im * 16 + r;
        int rowB = rowA + 8;
        const float* ga = nullptr; const float* gb = nullptr;
        if (gidx) {
            ga = Gadd + (size_t)gidx[rowA] * 256;
            gb = Gadd + (size_t)gidx[rowB] * 256;
        }
#pragma unroll
        for (int jn = 0; jn < 8; jn++) {
            int col = wn + jn * 8 + cc;
            float2 v0 = make_float2(acc[im][jn][0], acc[im][jn][1]);
            float2 v1 = make_float2(acc[im][jn][2], acc[im][jn][3]);
            if (gidx) {
                float2 a0 = *(const float2*)(ga + col);
                float2 a1 = *(const float2*)(gb + col);
                v0.x += a0.x; v0.y += a0.y; v1.x += a1.x; v1.y += a1.y;
            }
            *(float2*)(C + (size_t)rowA * 256 + col) = v0;
            *(float2*)(C + (size_t)rowB * 256 + col) = v1;
        }
    }
}

// ---------------- segment reductions -----------------------------------------
// segmean: also emits the tf32-rounded copy of x (each row visited exactly once)
__global__ __launch_bounds__(64)
void segmean_kernel(const float* __restrict__ x, const int* __restrict__ dom) {
    __shared__ int s_lo, s_hi;
    int d = blockIdx.x;
    if (threadIdx.x == 0) {
        s_lo = lower_bound_dev(dom, N_ATOMS, d);
        s_hi = lower_bound_dev(dom, N_ATOMS, d + 1);
    }
    __syncthreads();
    int lo = s_lo, hi = s_hi, c = threadIdx.x;
    float4 s = make_float4(0.f, 0.f, 0.f, 0.f);
    for (int r = lo; r < hi; r++) {
        float4 v = ((const float4*)x)[(size_t)r * 64 + c];
        float4 t = make_float4(to_tf32(v.x), to_tf32(v.y), to_tf32(v.z), to_tf32(v.w));
        ((float4*)g_xc)[(size_t)r * 64 + c] = t;     // fused x -> tf32 copy
        s.x += v.x; s.y += v.y; s.z += v.z; s.w += v.w;
    }
    int cnt = hi - lo;
    float inv = 1.f / (float)(cnt > 0 ? cnt : 1);
    s.x = to_tf32(s.x * inv); s.y = to_tf32(s.y * inv);
    s.z = to_tf32(s.z * inv); s.w = to_tf32(s.w * inv);
    ((float4*)g_xinv)[(size_t)d * 64 + c] = s;
}

// segmsg: computes msg[m]; fused dom_scatter: r1[dme1] += msg, r2[dme1] += xinv[dme0]
__global__ __launch_bounds__(64)
void segmsg_kernel(const float* __restrict__ x, const int* __restrict__ ii,
                   const int* __restrict__ src, const int* __restrict__ dme) {
    __shared__ int s_lo, s_hi;
    int m = blockIdx.x;
    if (threadIdx.x == 0) {
        s_lo = lower_bound_dev(ii, E_EDGE, m);
        s_hi = lower_bound_dev(ii, E_EDGE, m + 1);
    }
    __syncthreads();
    int lo = s_lo, hi = s_hi, c = threadIdx.x;
    float4 s = make_float4(0.f, 0.f, 0.f, 0.f);
    for (int e = lo; e < hi; e++) {
        float4 v = ((const float4*)x)[(size_t)src[e] * 64 + c];
        s.x += v.x; s.y += v.y; s.z += v.z; s.w += v.w;
    }
    s.x = to_tf32(s.x); s.y = to_tf32(s.y); s.z = to_tf32(s.z); s.w = to_tf32(s.w);
    ((float4*)g_msg)[(size_t)m * 64 + c] = s;
    // fused domain scatter
    int d0 = dme[m];
    int d1 = dme[M_MSG + m];
    float4 b = ((const float4*)g_xinv)[(size_t)d0 * 64 + c];
    red_add_v4(&g_r1[((size_t)d1 * 64 + c) * 4], s);
    red_add_v4(&g_r2[((size_t)d1 * 64 + c) * 4], b);
}

// out[tgt[e]] += xa[src[e]] + msgb[ii[e]]    (msgb already includes u2[dme0])
__global__ void edge_scatter_kernel(const int* __restrict__ nme, const int* __restrict__ ii,
                                    float* __restrict__ out) {
    int e = blockIdx.x * 4 + (threadIdx.x >> 6);
    int c = threadIdx.x & 63;
    int s = nme[e];
    int t = nme[E_EDGE + e];
    int m = ii[e];
    float4 a = ((const float4*)g_xa)[(size_t)s * 64 + c];
    float4 b = ((const float4*)g_msgb)[(size_t)m * 64 + c];
    float4 v = make_float4(a.x + b.x, a.y + b.y, a.z + b.z, a.w + b.w);
    red_add_v4(out + (size_t)t * 256 + c * 4, v);
}

// ---------------- launch ------------------------------------------------------
extern "C" void kernel_launch(void* const* d_in, const int* in_sizes, int n_in,
                              void* d_out, int out_size) {
    const float* x        = (const float*)d_in[0];
    const int*   dom      = (const int*)d_in[1];
    const int*   nme      = (const int*)d_in[2];   // [2, E] : src then tgt
    const int*   ii       = (const int*)d_in[3];
    const int*   dme      = (const int*)d_in[4];   // [2, M] : dme0 then dme1
    const float* Wtf_int  = (const float*)d_in[5]; // [256, 768]
    const float* Wtf_inv  = (const float*)d_in[6]; // [256, 512]
    const float* Wlin_inv = (const float*)d_in[7]; // [256, 256]
    const float* Wlin_id  = (const float*)d_in[8]; // [256, 256]
    float* out = (float*)d_out;

    float *xc, *wc, *xa, *msg, *msgb, *xinv, *u2, *r1, *r2, *invt;
    cudaGetSymbolAddress((void**)&xc,   g_xc);
    cudaGetSymbolAddress((void**)&wc,   g_wc);
    cudaGetSymbolAddress((void**)&xa,   g_xa);
    cudaGetSymbolAddress((void**)&msg,  g_msg);
    cudaGetSymbolAddress((void**)&msgb, g_msgb);
    cudaGetSymbolAddress((void**)&xinv, g_xinv);
    cudaGetSymbolAddress((void**)&u2,   g_u2);
    cudaGetSymbolAddress((void**)&r1,   g_r1);
    cudaGetSymbolAddress((void**)&r2,   g_r2);
    cudaGetSymbolAddress((void**)&invt, g_invt);

    cudaFuncSetAttribute(mma_gemm, cudaFuncAttributeMaxDynamicSharedMemorySize, SMEMSZ);

    // pre-round weights to tf32 (tiny)
    conv4_kernel<<<192, 256>>>(Wtf_int,  wc + WC_TFI);
    conv4_kernel<<<128, 256>>>(Wtf_inv,  wc + WC_TFV);
    conv4_kernel<<<64,  256>>>(Wlin_inv, wc + WC_LINV);
    conv4_kernel<<<64,  256>>>(Wlin_id,  wc + WC_LID);

    // r1/r2 zero, then fused segment reductions
    cudaMemsetAsync(r1, 0, (size_t)D_DOM * CH * sizeof(float), 0);
    cudaMemsetAsync(r2, 0, (size_t)D_DOM * CH * sizeof(float), 0);
    segmean_kernel<<<D_DOM, 64>>>(x, dom);               // also writes g_xc
    segmsg_kernel<<<M_MSG, 64>>>(x, ii, nme, dme);       // also scatters r1/r2

    // u2 = xinv@W2^T
    mma_gemm<<<D_DOM / 128, 512, SMEMSZ>>>(xinv, wc + WC_TFI + 512, 768,
                                           nullptr, nullptr, 0, nullptr, nullptr, 0,
                                           u2, nullptr, nullptr);
    // invt = xinv@Wlin_inv^T + r1@W4a^T + r2@W4b^T   (triple-A GEMM)
    mma_gemm<<<D_DOM / 128, 512, SMEMSZ>>>(xinv, wc + WC_LINV, 256,
                                           r1, wc + WC_TFV, 512,
                                           r2, wc + WC_TFV + 256, 512,
                                           invt, nullptr, nullptr);
    // out = x@Wlin_id^T + invt[dom]   (epilogue gather-add)
    mma_gemm<<<N_ATOMS / 128, 512, SMEMSZ>>>(xc, wc + WC_LID, 256,
                                             nullptr, nullptr, 0, nullptr, nullptr, 0,
                                             out, invt, dom);
    // xa = x@W0^T
    mma_gemm<<<N_ATOMS / 128, 512, SMEMSZ>>>(xc, wc + WC_TFI, 768,
                                             nullptr, nullptr, 0, nullptr, nullptr, 0,
                                             xa, nullptr, nullptr);
    // msgb = msg@W1^T + u2[dme0]   (fused gather-add epilogue)
    mma_gemm<<<M_MSG / 128, 512, SMEMSZ>>>(msg, wc + WC_TFI + 256, 768,
                                           nullptr, nullptr, 0, nullptr, nullptr, 0,
                                           msgb, u2, dme);

    // single fused edge scatter
    edge_scatter_kernel<<<E_EDGE / 4, 256>>>(nme, ii, out);
}

// round 17
// speedup vs baseline: 1.0831x; 1.0622x over previous
#include <cuda_runtime.h>
#include <cstdint>

#define N_ATOMS 131072
#define CH      256
#define D_DOM   16384
#define M_MSG   65536
#define E_EDGE  262144

// ---------------- scratch (device globals; no allocations allowed) ----------
__device__ float g_xa[(size_t)N_ATOMS * CH];   // x @ W0^T
__device__ float g_msg[(size_t)M_MSG * CH];    // segsum(x[src], ii)
__device__ float g_msgb[(size_t)M_MSG * CH];   // msg @ W1^T + u2[dme0]  (fused epilogue)
__device__ float g_xinv[(size_t)D_DOM * CH];   // segmean(x, dom)
__device__ float g_u2[(size_t)D_DOM * CH];     // x_inv @ W2^T
__device__ float g_r1[(size_t)D_DOM * CH];     // segsum(msg, dme1)
__device__ float g_r2[(size_t)D_DOM * CH];     // segsum(x_inv[dme0], dme1)
__device__ float g_invt[(size_t)D_DOM * CH];   // xinv@Wlin_inv + r1@W4a + r2@W4b

// ---------------- helpers ----------------------------------------------------
__device__ __forceinline__ float to_tf32(float f) {
    float r; asm("cvt.rna.tf32.f32 %0, %1;" : "=f"(r) : "f"(f)); return r;
}
__device__ __forceinline__ void mma_tf32(float* c, const uint32_t* a, const uint32_t* b) {
    asm volatile("mma.sync.aligned.m16n8k8.row.col.f32.tf32.tf32.f32 "
                 "{%0,%1,%2,%3}, {%4,%5,%6,%7}, {%8,%9}, {%0,%1,%2,%3};"
                 : "+f"(c[0]), "+f"(c[1]), "+f"(c[2]), "+f"(c[3])
                 : "r"(a[0]), "r"(a[1]), "r"(a[2]), "r"(a[3]), "r"(b[0]), "r"(b[1]));
}
__device__ __forceinline__ int lower_bound_dev(const int* __restrict__ a, int n, int v) {
    int lo = 0, hi = n;
    while (lo < hi) { int mid = (lo + hi) >> 1; if (a[mid] < v) lo = mid + 1; else hi = mid; }
    return lo;
}
__device__ __forceinline__ void red_add_v4(float* p, float4 v) {
    asm volatile("red.global.add.v4.f32 [%0], {%1,%2,%3,%4};"
                 :: "l"(p), "f"(v.x), "f"(v.y), "f"(v.z), "f"(v.w) : "memory");
}

// ---------------- tf32 mma.sync GEMM (R14-proven core) ------------------------
// C[i,j] = sum_k A1[i,k]*B1[j,k] (+ A2@B2^T) (+ A3@B3^T); optional epilogue
// C[i,j] += Gadd[gidx[i]][j].  A leading dim = 256 (K=256). C is [M, 256].
// CTA tile 128x256; 8 warps 2x4; warp tile 64x64 = 4x8 m16n8k8 atoms.
// K chunked at 32, double-buffered SMEM, 36-float row stride.
#define ASTRIDE 36
#define ABUF (128 * ASTRIDE)
#define BBUF (256 * ASTRIDE)
#define SMEMSZ ((2 * ABUF + 2 * BBUF) * 4)

__global__ __launch_bounds__(256, 1)
void mma_gemm(const float* __restrict__ A1, const float* __restrict__ B1, int ldb1,
              const float* __restrict__ A2, const float* __restrict__ B2, int ldb2,
              const float* __restrict__ A3, const float* __restrict__ B3, int ldb3,
              float* __restrict__ C,
              const float* __restrict__ Gadd, const int* __restrict__ gidx)
{
    extern __shared__ float sm[];
    float* Asm = sm;                    // [2][128][36]
    float* Bsm = sm + 2 * ABUF;         // [2][256][36]

    int tid = threadIdx.x, lane = tid & 31, wid = tid >> 5;
    int wm = (wid >> 2) * 64, wn = (wid & 3) * 64;
    int row0 = blockIdx.x * 128;
    int rr = tid >> 3, c4 = tid & 7;    // load mapping: 32 rows x 8 float4 per pass
    int nch = 8 + (A2 ? 8 : 0) + (A3 ? 8 : 0);

    float acc[4][8][4];
#pragma unroll
    for (int i = 0; i < 4; i++)
#pragma unroll
        for (int j = 0; j < 8; j++)
#pragma unroll
            for (int q = 0; q < 4; q++) acc[i][j][q] = 0.f;

    float4 ra[4], rb[8];

    auto issue_load = [&](int kc) {
        const float* A = (kc < 8) ? A1 : (kc < 16) ? A2 : A3;
        const float* B = (kc < 8) ? B1 : (kc < 16) ? B2 : B3;
        int ldb = (kc < 8) ? ldb1 : (kc < 16) ? ldb2 : ldb3;
        int k0 = (kc & 7) * 32;
#pragma unroll
        for (int p = 0; p < 4; p++)
            ra[p] = *(const float4*)(A + (size_t)(row0 + p * 32 + rr) * 256 + k0 + c4 * 4);
#pragma unroll
        for (int p = 0; p < 8; p++)
            rb[p] = *(const float4*)(B + (size_t)(p * 32 + rr) * ldb + k0 + c4 * 4);
    };
    auto store_smem = [&](int buf) {
        float* a = Asm + buf * ABUF;
        float* b = Bsm + buf * BBUF;
#pragma unroll
        for (int p = 0; p < 4; p++) {
            float4 v = ra[p];
            v.x = to_tf32(v.x); v.y = to_tf32(v.y); v.z = to_tf32(v.z); v.w = to_tf32(v.w);
            *(float4*)(a + (p * 32 + rr) * ASTRIDE + c4 * 4) = v;
        }
#pragma unroll
        for (int p = 0; p < 8; p++) {
            float4 v = rb[p];
            v.x = to_tf32(v.x); v.y = to_tf32(v.y); v.z = to_tf32(v.z); v.w = to_tf32(v.w);
            *(float4*)(b + (p * 32 + rr) * ASTRIDE + c4 * 4) = v;
        }
    };
    auto compute = [&](int buf) {
        const float* a = Asm + buf * ABUF;
        const float* b = Bsm + buf * BBUF;
        int r = lane >> 2, c = lane & 3;
#pragma unroll
        for (int kk = 0; kk < 4; kk++) {
            uint32_t af[4][4], bf[8][2];
#pragma unroll
            for (int im = 0; im < 4; im++) {
                const float* ap = a + (wm + im * 16 + r) * ASTRIDE + kk * 8 + c;
                af[im][0] = __float_as_uint(ap[0]);
                af[im][1] = __float_as_uint(ap[8 * ASTRIDE]);
                af[im][2] = __float_as_uint(ap[4]);
                af[im][3] = __float_as_uint(ap[8 * ASTRIDE + 4]);
            }
#pragma unroll
            for (int jn = 0; jn < 8; jn++) {
                const float* bp = b + (wn + jn * 8 + r) * ASTRIDE + kk * 8 + c;
                bf[jn][0] = __float_as_uint(bp[0]);
                bf[jn][1] = __float_as_uint(bp[4]);
            }
#pragma unroll
            for (int im = 0; im < 4; im++)
#pragma unroll
                for (int jn = 0; jn < 8; jn++)
                    mma_tf32(acc[im][jn], af[im], bf[jn]);
        }
    };

    issue_load(0);
    store_smem(0);
    __syncthreads();
    for (int kc = 0; kc < nch; kc++) {
        if (kc + 1 < nch) issue_load(kc + 1);
        compute(kc & 1);
        // store targets the OTHER buffer; its previous readers passed the
        // end-of-(kc-1) barrier, so no pre-store sync is needed.
        if (kc + 1 < nch) store_smem((kc + 1) & 1);
        __syncthreads();
    }

    // epilogue (+ optional gather-add of Gadd[gidx[row]])
    int r = lane >> 2, cc = (lane & 3) * 2;
#pragma unroll
    for (int im = 0; im < 4; im++) {
        int rowA = row0 + wm + im * 16 + r;
        int rowB = rowA + 8;
        const float* ga = nullptr; const float* gb = nullptr;
        if (gidx) {
            ga = Gadd + (size_t)gidx[rowA] * 256;
            gb = Gadd + (size_t)gidx[rowB] * 256;
        }
#pragma unroll
        for (int jn = 0; jn < 8; jn++) {
            int col = wn + jn * 8 + cc;
            float2 v0 = make_float2(acc[im][jn][0], acc[im][jn][1]);
            float2 v1 = make_float2(acc[im][jn][2], acc[im][jn][3]);
            if (gidx) {
                float2 a0 = *(const float2*)(ga + col);
                float2 a1 = *(const float2*)(gb + col);
                v0.x += a0.x; v0.y += a0.y; v1.x += a1.x; v1.y += a1.y;
            }
            *(float2*)(C + (size_t)rowA * 256 + col) = v0;
            *(float2*)(C + (size_t)rowB * 256 + col) = v1;
        }
    }
}

// ---------------- segment reductions: 64 threads, float4 per thread ----------
__global__ __launch_bounds__(64)
void segmean_kernel(const float* __restrict__ x, const int* __restrict__ dom) {
    __shared__ int s_lo, s_hi;
    int d = blockIdx.x;
    if (threadIdx.x == 0) {
        s_lo = lower_bound_dev(dom, N_ATOMS, d);
        s_hi = lower_bound_dev(dom, N_ATOMS, d + 1);
    }
    __syncthreads();
    int lo = s_lo, hi = s_hi, c = threadIdx.x;
    float4 s = make_float4(0.f, 0.f, 0.f, 0.f);
    for (int r = lo; r < hi; r++) {
        float4 v = ((const float4*)x)[(size_t)r * 64 + c];
        s.x += v.x; s.y += v.y; s.z += v.z; s.w += v.w;
    }
    int cnt = hi - lo;
    float inv = 1.f / (float)(cnt > 0 ? cnt : 1);
    s.x *= inv; s.y *= inv; s.z *= inv; s.w *= inv;
    ((float4*)g_xinv)[(size_t)d * 64 + c] = s;
}

// segmsg: computes msg[m]; fused dom_scatter: r1[dme1] += msg, r2[dme1] += xinv[dme0]
__global__ __launch_bounds__(64)
void segmsg_kernel(const float* __restrict__ x, const int* __restrict__ ii,
                   const int* __restrict__ src, const int* __restrict__ dme) {
    __shared__ int s_lo, s_hi;
    int m = blockIdx.x;
    if (threadIdx.x == 0) {
        s_lo = lower_bound_dev(ii, E_EDGE, m);
        s_hi = lower_bound_dev(ii, E_EDGE, m + 1);
    }
    __syncthreads();
    int lo = s_lo, hi = s_hi, c = threadIdx.x;
    float4 s = make_float4(0.f, 0.f, 0.f, 0.f);
    for (int e = lo; e < hi; e++) {
        float4 v = ((const float4*)x)[(size_t)src[e] * 64 + c];
        s.x += v.x; s.y += v.y; s.z += v.z; s.w += v.w;
    }
    ((float4*)g_msg)[(size_t)m * 64 + c] = s;
    // fused domain scatter
    int d0 = dme[m];
    int d1 = dme[M_MSG + m];
    float4 b = ((const float4*)g_xinv)[(size_t)d0 * 64 + c];
    red_add_v4(&g_r1[((size_t)d1 * 64 + c) * 4], s);
    red_add_v4(&g_r2[((size_t)d1 * 64 + c) * 4], b);
}

// out[tgt[e]] += xa[src[e]] + msgb[ii[e]]    (msgb already includes u2[dme0])
__global__ void edge_scatter_kernel(const int* __restrict__ nme, const int* __restrict__ ii,
                                    float* __restrict__ out) {
    int e = blockIdx.x * 4 + (threadIdx.x >> 6);
    int c = threadIdx.x & 63;
    int s = nme[e];
    int t = nme[E_EDGE + e];
    int m = ii[e];
    float4 a = ((const float4*)g_xa)[(size_t)s * 64 + c];
    float4 b = ((const float4*)g_msgb)[(size_t)m * 64 + c];
    float4 v = make_float4(a.x + b.x, a.y + b.y, a.z + b.z, a.w + b.w);
    red_add_v4(out + (size_t)t * 256 + c * 4, v);
}

// ---------------- launch ------------------------------------------------------
extern "C" void kernel_launch(void* const* d_in, const int* in_sizes, int n_in,
                              void* d_out, int out_size) {
    const float* x        = (const float*)d_in[0];
    const int*   dom      = (const int*)d_in[1];
    const int*   nme      = (const int*)d_in[2];   // [2, E] : src then tgt
    const int*   ii       = (const int*)d_in[3];
    const int*   dme      = (const int*)d_in[4];   // [2, M] : dme0 then dme1
    const float* Wtf_int  = (const float*)d_in[5]; // [256, 768]
    const float* Wtf_inv  = (const float*)d_in[6]; // [256, 512]
    const float* Wlin_inv = (const float*)d_in[7]; // [256, 256]
    const float* Wlin_id  = (const float*)d_in[8]; // [256, 256]
    float* out = (float*)d_out;

    float *xa, *msg, *msgb, *xinv, *u2, *r1, *r2, *invt;
    cudaGetSymbolAddress((void**)&xa,   g_xa);
    cudaGetSymbolAddress((void**)&msg,  g_msg);
    cudaGetSymbolAddress((void**)&msgb, g_msgb);
    cudaGetSymbolAddress((void**)&xinv, g_xinv);
    cudaGetSymbolAddress((void**)&u2,   g_u2);
    cudaGetSymbolAddress((void**)&r1,   g_r1);
    cudaGetSymbolAddress((void**)&r2,   g_r2);
    cudaGetSymbolAddress((void**)&invt, g_invt);

    cudaFuncSetAttribute(mma_gemm, cudaFuncAttributeMaxDynamicSharedMemorySize, SMEMSZ);

    // r1/r2 zero, then segment reductions (sorted indicators -> binary search)
    cudaMemsetAsync(r1, 0, (size_t)D_DOM * CH * sizeof(float), 0);
    cudaMemsetAsync(r2, 0, (size_t)D_DOM * CH * sizeof(float), 0);
    segmean_kernel<<<D_DOM, 64>>>(x, dom);
    segmsg_kernel<<<M_MSG, 64>>>(x, ii, nme, dme);   // also scatters r1/r2

    // u2 = xinv@W2^T
    mma_gemm<<<D_DOM / 128, 256, SMEMSZ>>>(xinv, Wtf_int + 512, 768,
                                           nullptr, nullptr, 0, nullptr, nullptr, 0,
                                           u2, nullptr, nullptr);
    // invt = xinv@Wlin_inv^T + r1@W4a^T + r2@W4b^T   (triple-A GEMM)
    mma_gemm<<<D_DOM / 128, 256, SMEMSZ>>>(xinv, Wlin_inv, 256,
                                           r1, Wtf_inv, 512,
                                           r2, Wtf_inv + 256, 512,
                                           invt, nullptr, nullptr);
    // out = x@Wlin_id^T + invt[dom]   (epilogue gather-add)
    mma_gemm<<<N_ATOMS / 128, 256, SMEMSZ>>>(x, Wlin_id, 256,
                                             nullptr, nullptr, 0, nullptr, nullptr, 0,
                                             out, invt, dom);
    // xa = x@W0^T
    mma_gemm<<<N_ATOMS / 128, 256, SMEMSZ>>>(x, Wtf_int, 768,
                                             nullptr, nullptr, 0, nullptr, nullptr, 0,
                                             xa, nullptr, nullptr);
    // msgb = msg@W1^T + u2[dme0]   (fused gather-add epilogue)
    mma_gemm<<<M_MSG / 128, 256, SMEMSZ>>>(msg, Wtf_int + 256, 768,
                                           nullptr, nullptr, 0, nullptr, nullptr, 0,
                                           msgb, u2, dme);

    // single fused edge scatter
    edge_scatter_kernel<<<E_EDGE / 4, 256>>>(nme, ii, out);
}